// round 12
// baseline (speedup 1.0000x reference)
#include <cuda_runtime.h>
#include <cuda_fp16.h>
#include <cstdint>

// ---------------- problem constants ----------------
constexpr int NODES  = 100000;
constexpr int EDGES  = 500000;
constexpr int FEAT   = 256;
constexpr int CLASSES = 349;
constexpr int NPAD_OUT = 384;
constexpr float NEG_SLOPE = 0.2f;
constexpr int GRID_M = (NODES + 127) / 128;   // 782

constexpr int TOTE = 3 * EDGES;               // 1.5M
constexpr int NSEG = 3 * NODES;               // 300k
constexpr int SBLK = 512;
constexpr int NBLK = (NSEG + SBLK - 1) / SBLK; // 586

// GEMM tiling
constexpr int STAGES = 3;
constexpr int TILE_BYTES = 128 * 80;
constexpr int STAGE_BYTES = 2 * TILE_BYTES;
constexpr int GEMM_SMEM = STAGES * STAGE_BYTES + 2048;

// ---------------- device scratch ----------------
__device__ __half g_feat[(size_t)2 * NODES * FEAT];   // fp16 feat, double-buffered by parity
__device__ float  g_agg[(size_t)NODES * FEAT];
__device__ float  g_el[2 * NODES * 4];
__device__ float  g_er[2 * NODES * 4];
__device__ __half g_ahi[(size_t)NODES * FEAT];
__device__ __half g_alo[(size_t)NODES * FEAT];
__device__ __half g_whi[6 * FEAT * FEAT];
__device__ __half g_wohi[NPAD_OUT * FEAT];
__device__ int    g_rowptr[NSEG + 1];
__device__ int    g_head[NSEG];
__device__ int    g_blksum[NBLK];
__device__ int    g_ssorted[TOTE];

// ---------------- helpers ----------------
__device__ __forceinline__ uint32_t smem_u32(const void* p) {
    uint32_t a;
    asm("{ .reg .u64 t; cvta.to.shared.u64 t, %1; cvt.u32.u64 %0, t; }" : "=r"(a) : "l"(p));
    return a;
}
__device__ __forceinline__ void cp16(uint32_t dst, const void* src, uint32_t sz) {
    asm volatile("cp.async.cg.shared.global [%0], [%1], 16, %2;"
                 :: "r"(dst), "l"(src), "r"(sz) : "memory");
}
__device__ __forceinline__ void cp_commit() { asm volatile("cp.async.commit_group;" ::: "memory"); }
__device__ __forceinline__ void cp_wait1()  { asm volatile("cp.async.wait_group 1;" ::: "memory"); }
__device__ __forceinline__ void cp_wait0()  { asm volatile("cp.async.wait_group 0;" ::: "memory"); }

__device__ __forceinline__ void ldmx4(uint32_t* r, uint32_t addr) {
    asm volatile("ldmatrix.sync.aligned.m8n8.x4.shared.b16 {%0,%1,%2,%3}, [%4];"
                 : "=r"(r[0]), "=r"(r[1]), "=r"(r[2]), "=r"(r[3]) : "r"(addr));
}
__device__ __forceinline__ void mma16816(float* d, const uint32_t* a,
                                         uint32_t b0, uint32_t b1) {
    asm volatile(
        "mma.sync.aligned.m16n8k16.row.col.f32.f16.f16.f32 "
        "{%0,%1,%2,%3}, {%4,%5,%6,%7}, {%8,%9}, {%0,%1,%2,%3};"
        : "+f"(d[0]), "+f"(d[1]), "+f"(d[2]), "+f"(d[3])
        : "r"(a[0]), "r"(a[1]), "r"(a[2]), "r"(a[3]), "r"(b0), "r"(b1));
}

// ---------------- CSR build ----------------
__global__ void __launch_bounds__(256) zero_i(int* __restrict__ p, int n) {
    int i = blockIdx.x * 256 + threadIdx.x;
    if (i < n) p[i] = 0;
}

__global__ void __launch_bounds__(256) hist_k(const int* __restrict__ dst,
                                              int* __restrict__ counts) {
    int i = blockIdx.x * 256 + threadIdx.x;
    if (i >= TOTE) return;
    int e = i / EDGES;
    atomicAdd(&counts[e * NODES + dst[i]], 1);
}

__global__ void __launch_bounds__(SBLK) scan_l1(const int* __restrict__ counts,
                                                int* __restrict__ rowptr,
                                                int* __restrict__ blksum) {
    __shared__ int s[SBLK];
    int t = threadIdx.x, b = blockIdx.x, i = b * SBLK + t;
    int v = (i < NSEG) ? counts[i] : 0;
    s[t] = v;
    __syncthreads();
    for (int o = 1; o < SBLK; o <<= 1) {
        int x = (t >= o) ? s[t - o] : 0;
        __syncthreads();
        s[t] += x;
        __syncthreads();
    }
    if (i < NSEG) rowptr[i] = s[t] - v;
    if (t == SBLK - 1) blksum[b] = s[t];
}

__global__ void __launch_bounds__(1024) scan_l2(int* __restrict__ blksum,
                                                int* __restrict__ rowptr) {
    __shared__ int s[1024];
    int t = threadIdx.x;
    int v = (t < NBLK) ? blksum[t] : 0;
    s[t] = v;
    __syncthreads();
    for (int o = 1; o < 1024; o <<= 1) {
        int x = (t >= o) ? s[t - o] : 0;
        __syncthreads();
        s[t] += x;
        __syncthreads();
    }
    if (t < NBLK) blksum[t] = s[t] - v;
    if (t == 0) rowptr[NSEG] = TOTE;
}

__global__ void __launch_bounds__(256) scan_l3(int* __restrict__ rowptr,
                                               const int* __restrict__ blksum,
                                               int* __restrict__ head) {
    int i = blockIdx.x * 256 + threadIdx.x;
    if (i >= NSEG) return;
    int v = rowptr[i] + blksum[i / SBLK];
    rowptr[i] = v;
    head[i] = v;
}

__global__ void __launch_bounds__(256) scatter_k(const int* __restrict__ src,
                                                 const int* __restrict__ dst,
                                                 int* __restrict__ head,
                                                 int* __restrict__ ssorted) {
    int i = blockIdx.x * 256 + threadIdx.x;
    if (i >= TOTE) return;
    int e = i / EDGES;
    int pos = atomicAdd(&head[e * NODES + dst[i]], 1);
    ssorted[pos] = src[i];
}

// ---------------- prep kernels ----------------
__global__ void __launch_bounds__(256) split_f32(
    const float* __restrict__ in, __half* __restrict__ hi,
    __half* __restrict__ lo, int n4)
{
    int i = blockIdx.x * blockDim.x + threadIdx.x;
    if (i >= n4) return;
    float4 v = reinterpret_cast<const float4*>(in)[i];
    __half h0 = __float2half_rn(v.x), h1 = __float2half_rn(v.y);
    __half h2 = __float2half_rn(v.z), h3 = __float2half_rn(v.w);
    __half l0 = __float2half_rn(v.x - __half2float(h0));
    __half l1 = __float2half_rn(v.y - __half2float(h1));
    __half l2 = __float2half_rn(v.z - __half2float(h2));
    __half l3 = __float2half_rn(v.w - __half2float(h3));
    __half2* ph = reinterpret_cast<__half2*>(hi);
    __half2* pl = reinterpret_cast<__half2*>(lo);
    ph[i * 2]     = __halves2half2(h0, h1);
    ph[i * 2 + 1] = __halves2half2(h2, h3);
    pl[i * 2]     = __halves2half2(l0, l1);
    pl[i * 2 + 1] = __halves2half2(l2, l3);
}

__global__ void __launch_bounds__(256) prep_w(
    const float* __restrict__ W, __half* __restrict__ hi)
{
    int idx = blockIdx.x * blockDim.x + threadIdx.x;
    if (idx >= 6 * FEAT * FEAT) return;
    int le = idx >> 16;
    int r  = idx & 0xffff;
    int n  = r >> 8;
    int k  = r & 255;
    hi[le * FEAT * FEAT + n * FEAT + k] = __float2half_rn(W[le * FEAT * FEAT + k * FEAT + n]);
}

__global__ void __launch_bounds__(256) prep_wout(
    const float* __restrict__ W_out, __half* __restrict__ hi)
{
    int idx = blockIdx.x * blockDim.x + threadIdx.x;
    if (idx >= NPAD_OUT * FEAT) return;
    int n = idx >> 8;
    int k = idx & 255;
    float v = (n < CLASSES) ? W_out[k * CLASSES + n] : 0.f;
    hi[n * FEAT + k] = __float2half_rn(v);
}

// ---------------- tensor-core GEMM (+ fused attention dots) ----------------
// If Ch != null: write fp16 output (feat), row length FEAT. Else fp32 to C.
__global__ void __launch_bounds__(256, 2) gemm_mma(
    const __half* __restrict__ Ahi, const __half* __restrict__ Alo,
    const __half* __restrict__ B, float* __restrict__ C, __half* __restrict__ Ch,
    const float* __restrict__ bias, int M, int Ncols,
    const float* __restrict__ al, const float* __restrict__ ar,
    float* __restrict__ elO, float* __restrict__ erO)
{
    extern __shared__ char smem[];
    const uint32_t sbase = smem_u32(smem);
    const int tid = threadIdx.x;
    const int lane = tid & 31;
    const int warp = tid >> 5;
    const int wm = (warp & 1) * 64;
    const int wn = (warp >> 1) * 32;
    const long bm = (long)blockIdx.x * 128;
    const int bn  = blockIdx.y * 128;

    float acc[4][4][4];
#pragma unroll
    for (int i = 0; i < 4; i++)
#pragma unroll
        for (int j = 0; j < 4; j++)
#pragma unroll
            for (int q = 0; q < 4; q++) acc[i][j][q] = 0.f;

    const int NITER = 16;

    auto issue = [&](int it) {
        const int p  = it >> 3;
        const int kc = it & 7;
        const __half* Ag = (p == 0) ? Ahi : Alo;
        const uint32_t sa = sbase + (it % STAGES) * STAGE_BYTES;
        const uint32_t sb = sa + TILE_BYTES;
#pragma unroll
        for (int q = 0; q < 2; q++) {
            int ix = tid * 2 + q;
            int row = ix >> 2;
            int ch  = ix & 3;
            long arow = bm + row;
            long arc = arow < (M - 1) ? arow : (M - 1);
            cp16(sa + row * 80 + ch * 16, Ag + arc * 256 + kc * 32 + ch * 8,
                 (arow < M) ? 16u : 0u);
            cp16(sb + row * 80 + ch * 16, B + (long)(bn + row) * 256 + kc * 32 + ch * 8, 16u);
        }
        cp_commit();
    };

    issue(0);
    issue(1);

    for (int it = 0; it < NITER; it++) {
        cp_wait1();
        __syncthreads();   // also orders buffer reuse: issue(it+2) overwrites the
                           // buffer read at it-1, whose readers all passed this sync
        if (it + 2 < NITER) issue(it + 2);

        const uint32_t sa = sbase + (it % STAGES) * STAGE_BYTES;
        const uint32_t sb = sa + TILE_BYTES;
#pragma unroll
        for (int ks = 0; ks < 2; ks++) {
            uint32_t a[4][4];
#pragma unroll
            for (int mt = 0; mt < 4; mt++)
                ldmx4(a[mt], sa + (wm + mt * 16 + (lane & 15)) * 80
                              + ks * 32 + (lane >> 4) * 16);
            uint32_t b[2][4];
#pragma unroll
            for (int jb = 0; jb < 2; jb++)
                ldmx4(b[jb], sb + (wn + jb * 16 + ((lane >> 4) << 3) + (lane & 7)) * 80
                              + ks * 32 + ((lane >> 3) & 1) * 16);
#pragma unroll
            for (int mt = 0; mt < 4; mt++)
#pragma unroll
                for (int nt = 0; nt < 4; nt++)
                    mma16816(acc[mt][nt], a[mt],
                             b[nt >> 1][(nt & 1) * 2], b[nt >> 1][(nt & 1) * 2 + 1]);
        }
        // no trailing sync needed (see comment at top-of-loop sync)
    }
    cp_wait0();

    // epilogue (+ fused attention dots)
    float* elacc = reinterpret_cast<float*>(smem + STAGES * STAGE_BYTES);
    float* eracc = elacc + 256;
    float alv[8], arv[8];
    float pel[4][2] = {}, per_[4][2] = {};
    if (al) {
        elacc[tid] = 0.f; eracc[tid] = 0.f;
#pragma unroll
        for (int nt = 0; nt < 4; nt++) {
            int c0 = bn + wn + nt * 8 + (lane & 3) * 2;
            alv[nt * 2]     = al[c0];
            alv[nt * 2 + 1] = al[c0 + 1];
            arv[nt * 2]     = ar[c0];
            arv[nt * 2 + 1] = ar[c0 + 1];
        }
        __syncthreads();
    }

    const bool even = ((Ncols & 1) == 0);
#pragma unroll
    for (int mt = 0; mt < 4; mt++) {
#pragma unroll
        for (int nt = 0; nt < 4; nt++) {
            int c0 = bn + wn + nt * 8 + (lane & 3) * 2;
            float b0 = 0.f, b1 = 0.f;
            if (bias) {
                if (c0 < Ncols)     b0 = bias[c0];
                if (c0 + 1 < Ncols) b1 = bias[c0 + 1];
            }
#pragma unroll
            for (int half = 0; half < 2; half++) {
                long row = bm + wm + mt * 16 + (lane >> 2) + half * 8;
                float v0 = acc[mt][nt][half * 2 + 0];
                float v1 = acc[mt][nt][half * 2 + 1];
                if (al) {
                    pel[mt][half]  += v0 * alv[nt * 2] + v1 * alv[nt * 2 + 1];
                    per_[mt][half] += v0 * arv[nt * 2] + v1 * arv[nt * 2 + 1];
                }
                if (row >= M) continue;
                if (Ch) {
                    *reinterpret_cast<__half2*>(Ch + row * FEAT + c0) =
                        __floats2half2_rn(v0, v1);
                } else {
                    v0 += b0; v1 += b1;
                    float* crow = C + row * Ncols;
                    if (even && (c0 + 1) < Ncols) {
                        *reinterpret_cast<float2*>(crow + c0) = make_float2(v0, v1);
                    } else {
                        if (c0 < Ncols)     crow[c0] = v0;
                        if (c0 + 1 < Ncols) crow[c0 + 1] = v1;
                    }
                }
            }
        }
    }

    if (al) {
#pragma unroll
        for (int mt = 0; mt < 4; mt++)
#pragma unroll
            for (int half = 0; half < 2; half++) {
                float s1 = pel[mt][half], s2 = per_[mt][half];
                s1 += __shfl_xor_sync(0xffffffffu, s1, 1);
                s1 += __shfl_xor_sync(0xffffffffu, s1, 2);
                s2 += __shfl_xor_sync(0xffffffffu, s2, 1);
                s2 += __shfl_xor_sync(0xffffffffu, s2, 2);
                if ((lane & 3) == 0) {
                    int rl = wm + mt * 16 + (lane >> 2) + half * 8;
                    int hl = wn >> 6;
                    atomicAdd(&elacc[rl * 2 + hl], s1);
                    atomicAdd(&eracc[rl * 2 + hl], s2);
                }
            }
        __syncthreads();
        {
            int rl = tid >> 1, hl = tid & 1;
            long n = bm + rl;
            if (n < M) {
                int hg = (bn >> 6) + hl;
                elO[n * 4 + hg] = elacc[tid];
                erO[n * 4 + hg] = eracc[tid];
            }
        }
    }
}

// ---------------- CSR aggregation: one warp per dst node (fp16 feat gather) ----
// Each lane owns 8 consecutive dims: [lane*8, lane*8+8); head = lane>>3.
__global__ void __launch_bounds__(256) agg_csr(
    const int* __restrict__ rowptr_e, const int* __restrict__ ssorted,
    const float* __restrict__ el, const float* __restrict__ er,
    const __half* __restrict__ feat, float* __restrict__ agg,
    int mode, const float* __restrict__ bias_l,
    __half* __restrict__ hi, __half* __restrict__ lo, int do_relu)
{
    int d = blockIdx.x * 8 + (threadIdx.x >> 5);
    if (d >= NODES) return;
    int lane = threadIdx.x & 31;
    int beg = rowptr_e[d], end = rowptr_e[d + 1];
    float erl = (lane < 4) ? er[(size_t)d * 4 + lane] : 0.f;
    int hsel = lane >> 3;

    float acc[8] = {};
    float den = 0.f;

    for (int i = beg; i < end; i++) {
        int s = ssorted[i];
        float exv = 0.f;
        if (lane < 4) {
            float lg = el[(size_t)s * 4 + lane] + erl;
            lg = lg > 0.f ? lg : NEG_SLOPE * lg;
            exv = __expf(lg);
            den += exv;
        }
        float ev = __shfl_sync(0xffffffffu, exv, hsel);
        uint4 fv = *reinterpret_cast<const uint4*>(feat + (size_t)s * FEAT + lane * 8);
        float2 f0 = __half22float2(*reinterpret_cast<__half2*>(&fv.x));
        float2 f1 = __half22float2(*reinterpret_cast<__half2*>(&fv.y));
        float2 f2 = __half22float2(*reinterpret_cast<__half2*>(&fv.z));
        float2 f3 = __half22float2(*reinterpret_cast<__half2*>(&fv.w));
        acc[0] += ev * f0.x; acc[1] += ev * f0.y;
        acc[2] += ev * f1.x; acc[3] += ev * f1.y;
        acc[4] += ev * f2.x; acc[5] += ev * f2.y;
        acc[6] += ev * f3.x; acc[7] += ev * f3.y;
    }

    float dh = __shfl_sync(0xffffffffu, den, hsel);
    float r = (dh > 0.f) ? (1.0f / dh) : 0.f;
#pragma unroll
    for (int q = 0; q < 8; q++) acc[q] *= r;

    float4* ag = reinterpret_cast<float4*>(agg + (size_t)d * FEAT) + lane * 2;
    if (mode >= 1) {
        float4 p0 = ag[0], p1 = ag[1];
        acc[0] += p0.x; acc[1] += p0.y; acc[2] += p0.z; acc[3] += p0.w;
        acc[4] += p1.x; acc[5] += p1.y; acc[6] += p1.z; acc[7] += p1.w;
    }
    if (mode < 2) {
        ag[0] = make_float4(acc[0], acc[1], acc[2], acc[3]);
        ag[1] = make_float4(acc[4], acc[5], acc[6], acc[7]);
        return;
    }

    // final etype: add summed bias, relu, fp16 hi/lo split
    int c = lane * 8;
#pragma unroll
    for (int q = 0; q < 8; q++)
        acc[q] += bias_l[c + q] + bias_l[256 + c + q] + bias_l[512 + c + q];
    if (do_relu) {
#pragma unroll
        for (int q = 0; q < 8; q++) acc[q] = fmaxf(acc[q], 0.f);
    }
    __half2* ph = reinterpret_cast<__half2*>(hi + (size_t)d * FEAT + c);
    __half2* pl = reinterpret_cast<__half2*>(lo + (size_t)d * FEAT + c);
#pragma unroll
    for (int q = 0; q < 4; q++) {
        __half ha = __float2half_rn(acc[q * 2]);
        __half hb = __float2half_rn(acc[q * 2 + 1]);
        ph[q] = __halves2half2(ha, hb);
        pl[q] = __halves2half2(__float2half_rn(acc[q * 2] - __half2float(ha)),
                               __float2half_rn(acc[q * 2 + 1] - __half2float(hb)));
    }
}

// ---------------- launch ----------------
extern "C" void kernel_launch(void* const* d_in, const int* in_sizes, int n_in,
                              void* d_out, int out_size)
{
    const float* x      = (const float*)d_in[0];
    const float* W      = (const float*)d_in[1];
    const float* attn_l = (const float*)d_in[2];
    const float* attn_r = (const float*)d_in[3];
    const float* bias   = (const float*)d_in[4];
    const float* W_out  = (const float*)d_in[5];
    const float* b_out  = (const float*)d_in[6];
    const int*   src    = (const int*)d_in[7];
    const int*   dst    = (const int*)d_in[8];

    float *agg, *el, *er;
    __half *feat, *ahi, *alo, *whi, *wohi;
    int *rowptr, *head, *blksum, *ssorted;
    cudaGetSymbolAddress((void**)&feat,    g_feat);
    cudaGetSymbolAddress((void**)&agg,     g_agg);
    cudaGetSymbolAddress((void**)&el,      g_el);
    cudaGetSymbolAddress((void**)&er,      g_er);
    cudaGetSymbolAddress((void**)&ahi,     g_ahi);
    cudaGetSymbolAddress((void**)&alo,     g_alo);
    cudaGetSymbolAddress((void**)&whi,     g_whi);
    cudaGetSymbolAddress((void**)&wohi,    g_wohi);
    cudaGetSymbolAddress((void**)&rowptr,  g_rowptr);
    cudaGetSymbolAddress((void**)&head,    g_head);
    cudaGetSymbolAddress((void**)&blksum,  g_blksum);
    cudaGetSymbolAddress((void**)&ssorted, g_ssorted);

    cudaFuncSetAttribute(gemm_mma, cudaFuncAttributeMaxDynamicSharedMemorySize, GEMM_SMEM);

    // lazy one-time stream/event setup (first call = uncaptured correctness run)
    static cudaStream_t s1 = nullptr;
    static cudaEvent_t evStart, evGemm[6], evAgg[6], evLayer[2];
    if (!s1) {
        cudaStreamCreateWithFlags(&s1, cudaStreamNonBlocking);
        cudaEventCreateWithFlags(&evStart, cudaEventDisableTiming);
        for (int i = 0; i < 6; i++) {
            cudaEventCreateWithFlags(&evGemm[i], cudaEventDisableTiming);
            cudaEventCreateWithFlags(&evAgg[i],  cudaEventDisableTiming);
        }
        for (int i = 0; i < 2; i++) cudaEventCreateWithFlags(&evLayer[i], cudaEventDisableTiming);
    }

    // fork side stream from capture stream
    cudaEventRecord(evStart, 0);
    cudaStreamWaitEvent(s1, evStart, 0);

    // main stream: weight/input prep
    prep_w<<<(6 * FEAT * FEAT + 255) / 256, 256>>>(W, whi);
    prep_wout<<<(NPAD_OUT * FEAT + 255) / 256, 256>>>(W_out, wohi);
    split_f32<<<(NODES * FEAT / 4 + 255) / 256, 256>>>(x, ahi, alo, NODES * FEAT / 4);

    // side stream: CSR build (overlaps prep + first GEMM)
    zero_i<<<(NSEG + 255) / 256, 256, 0, s1>>>(head, NSEG);
    hist_k<<<(TOTE + 255) / 256, 256, 0, s1>>>(dst, head);
    scan_l1<<<NBLK, SBLK, 0, s1>>>(head, rowptr, blksum);
    scan_l2<<<1, 1024, 0, s1>>>(blksum, rowptr);
    scan_l3<<<(NSEG + 255) / 256, 256, 0, s1>>>(rowptr, blksum, head);
    scatter_k<<<(TOTE + 255) / 256, 256, 0, s1>>>(src, dst, head, ssorted);

    dim3 feat_grid(GRID_M, 2);
    dim3 out_grid(GRID_M, 3);
    const int AGG_BLOCKS = (NODES + 7) / 8;

    for (int l = 0; l < 2; l++) {
        for (int e = 0; e < 3; e++) {
            int le = l * 3 + e;
            int pb = e & 1;
            __half* feat_e = feat + (size_t)pb * NODES * FEAT;
            float* el_e = el + (size_t)pb * NODES * 4;
            float* er_e = er + (size_t)pb * NODES * 4;
            // ANTI-RACE: gemm(e=2) reuses parity-0 buffers still read by agg(e=0)
            if (e == 2) cudaStreamWaitEvent(0, evAgg[l * 3], 0);
            gemm_mma<<<feat_grid, 256, GEMM_SMEM>>>(
                ahi, alo, whi + (size_t)le * FEAT * FEAT, nullptr, feat_e, nullptr,
                NODES, FEAT,
                attn_l + le * FEAT, attn_r + le * FEAT, el_e, er_e);
            cudaEventRecord(evGemm[le], 0);
            cudaStreamWaitEvent(s1, evGemm[le], 0);
            agg_csr<<<AGG_BLOCKS, 256, 0, s1>>>(
                rowptr + e * NODES, ssorted, el_e, er_e, feat_e, agg,
                e, bias + l * 3 * FEAT, ahi, alo, (l == 0) ? 1 : 0);
            cudaEventRecord(evAgg[le], s1);
        }
        // layer boundary: main must wait for agg2 (writes ahi/alo)
        cudaEventRecord(evLayer[l], s1);
        cudaStreamWaitEvent(0, evLayer[l], 0);
    }

    gemm_mma<<<out_grid, 256, GEMM_SMEM>>>(
        ahi, alo, wohi, (float*)d_out, nullptr, b_out, NODES, CLASSES,
        nullptr, nullptr, nullptr, nullptr);
}

// round 16
// speedup vs baseline: 1.3244x; 1.3244x over previous
#include <cuda_runtime.h>
#include <cuda_fp16.h>
#include <cstdint>

// ---------------- problem constants ----------------
constexpr int NODES  = 100000;
constexpr int EDGES  = 500000;
constexpr int FEAT   = 256;
constexpr int CLASSES = 349;
constexpr int NPAD_OUT = 384;
constexpr float NEG_SLOPE = 0.2f;
constexpr int GRID_M = (NODES + 127) / 128;   // 782

constexpr int TOTE = 3 * EDGES;               // 1.5M
constexpr int NSEG = 3 * NODES;               // 300k
constexpr int SBLK = 512;
constexpr int NBLK = (NSEG + SBLK - 1) / SBLK; // 586

// GEMM tiling
constexpr int STAGES = 3;
constexpr int TILE_BYTES = 128 * 80;
constexpr int STAGE_BYTES = 2 * TILE_BYTES;
constexpr int GEMM_SMEM = STAGES * STAGE_BYTES + 2048;

// ---------------- device scratch ----------------
__device__ __half g_feat[(size_t)2 * NODES * FEAT];   // fp16 feat, double-buffered by parity
__device__ float  g_agg[(size_t)NODES * FEAT];
__device__ float  g_el[2 * NODES * 4];
__device__ float  g_er[2 * NODES * 4];
__device__ __half g_ah[(size_t)NODES * FEAT];         // fp16 hidden state (GEMM A)
__device__ __half g_whi[6 * FEAT * FEAT];
__device__ __half g_wohi[NPAD_OUT * FEAT];
__device__ int    g_rowptr[NSEG + 1];
__device__ int    g_head[NSEG];
__device__ int    g_blksum[NBLK];
__device__ int    g_ssorted[TOTE];

// ---------------- helpers ----------------
__device__ __forceinline__ uint32_t smem_u32(const void* p) {
    uint32_t a;
    asm("{ .reg .u64 t; cvta.to.shared.u64 t, %1; cvt.u32.u64 %0, t; }" : "=r"(a) : "l"(p));
    return a;
}
__device__ __forceinline__ void cp16(uint32_t dst, const void* src, uint32_t sz) {
    asm volatile("cp.async.cg.shared.global [%0], [%1], 16, %2;"
                 :: "r"(dst), "l"(src), "r"(sz) : "memory");
}
__device__ __forceinline__ void cp_commit() { asm volatile("cp.async.commit_group;" ::: "memory"); }
__device__ __forceinline__ void cp_wait1()  { asm volatile("cp.async.wait_group 1;" ::: "memory"); }
__device__ __forceinline__ void cp_wait0()  { asm volatile("cp.async.wait_group 0;" ::: "memory"); }

__device__ __forceinline__ void ldmx4(uint32_t* r, uint32_t addr) {
    asm volatile("ldmatrix.sync.aligned.m8n8.x4.shared.b16 {%0,%1,%2,%3}, [%4];"
                 : "=r"(r[0]), "=r"(r[1]), "=r"(r[2]), "=r"(r[3]) : "r"(addr));
}
__device__ __forceinline__ void mma16816(float* d, const uint32_t* a,
                                         uint32_t b0, uint32_t b1) {
    asm volatile(
        "mma.sync.aligned.m16n8k16.row.col.f32.f16.f16.f32 "
        "{%0,%1,%2,%3}, {%4,%5,%6,%7}, {%8,%9}, {%0,%1,%2,%3};"
        : "+f"(d[0]), "+f"(d[1]), "+f"(d[2]), "+f"(d[3])
        : "r"(a[0]), "r"(a[1]), "r"(a[2]), "r"(a[3]), "r"(b0), "r"(b1));
}

// ---------------- CSR build ----------------
__global__ void __launch_bounds__(256) zero_i(int* __restrict__ p, int n) {
    int i = blockIdx.x * 256 + threadIdx.x;
    if (i < n) p[i] = 0;
}

__global__ void __launch_bounds__(256) hist_k(const int* __restrict__ dst,
                                              int* __restrict__ counts) {
    int i = blockIdx.x * 256 + threadIdx.x;
    if (i >= TOTE) return;
    int e = i / EDGES;
    atomicAdd(&counts[e * NODES + dst[i]], 1);
}

__global__ void __launch_bounds__(SBLK) scan_l1(const int* __restrict__ counts,
                                                int* __restrict__ rowptr,
                                                int* __restrict__ blksum) {
    __shared__ int s[SBLK];
    int t = threadIdx.x, b = blockIdx.x, i = b * SBLK + t;
    int v = (i < NSEG) ? counts[i] : 0;
    s[t] = v;
    __syncthreads();
    for (int o = 1; o < SBLK; o <<= 1) {
        int x = (t >= o) ? s[t - o] : 0;
        __syncthreads();
        s[t] += x;
        __syncthreads();
    }
    if (i < NSEG) rowptr[i] = s[t] - v;
    if (t == SBLK - 1) blksum[b] = s[t];
}

__global__ void __launch_bounds__(1024) scan_l2(int* __restrict__ blksum,
                                                int* __restrict__ rowptr) {
    __shared__ int s[1024];
    int t = threadIdx.x;
    int v = (t < NBLK) ? blksum[t] : 0;
    s[t] = v;
    __syncthreads();
    for (int o = 1; o < 1024; o <<= 1) {
        int x = (t >= o) ? s[t - o] : 0;
        __syncthreads();
        s[t] += x;
        __syncthreads();
    }
    if (t < NBLK) blksum[t] = s[t] - v;
    if (t == 0) rowptr[NSEG] = TOTE;
}

__global__ void __launch_bounds__(256) scan_l3(int* __restrict__ rowptr,
                                               const int* __restrict__ blksum,
                                               int* __restrict__ head) {
    int i = blockIdx.x * 256 + threadIdx.x;
    if (i >= NSEG) return;
    int v = rowptr[i] + blksum[i / SBLK];
    rowptr[i] = v;
    head[i] = v;
}

__global__ void __launch_bounds__(256) scatter_k(const int* __restrict__ src,
                                                 const int* __restrict__ dst,
                                                 int* __restrict__ head,
                                                 int* __restrict__ ssorted) {
    int i = blockIdx.x * 256 + threadIdx.x;
    if (i >= TOTE) return;
    int e = i / EDGES;
    int pos = atomicAdd(&head[e * NODES + dst[i]], 1);
    ssorted[pos] = src[i];
}

// ---------------- prep kernels ----------------
__global__ void __launch_bounds__(256) conv_f32(
    const float* __restrict__ in, __half* __restrict__ hi, int n4)
{
    int i = blockIdx.x * blockDim.x + threadIdx.x;
    if (i >= n4) return;
    float4 v = reinterpret_cast<const float4*>(in)[i];
    __half2* ph = reinterpret_cast<__half2*>(hi);
    ph[i * 2]     = __floats2half2_rn(v.x, v.y);
    ph[i * 2 + 1] = __floats2half2_rn(v.z, v.w);
}

__global__ void __launch_bounds__(256) prep_w(
    const float* __restrict__ W, __half* __restrict__ hi)
{
    int idx = blockIdx.x * blockDim.x + threadIdx.x;
    if (idx >= 6 * FEAT * FEAT) return;
    int le = idx >> 16;
    int r  = idx & 0xffff;
    int n  = r >> 8;
    int k  = r & 255;
    hi[le * FEAT * FEAT + n * FEAT + k] = __float2half_rn(W[le * FEAT * FEAT + k * FEAT + n]);
}

__global__ void __launch_bounds__(256) prep_wout(
    const float* __restrict__ W_out, __half* __restrict__ hi)
{
    int idx = blockIdx.x * blockDim.x + threadIdx.x;
    if (idx >= NPAD_OUT * FEAT) return;
    int n = idx >> 8;
    int k = idx & 255;
    float v = (n < CLASSES) ? W_out[k * CLASSES + n] : 0.f;
    hi[n * FEAT + k] = __float2half_rn(v);
}

// ---------------- tensor-core GEMM (single-pass fp16, + fused attention dots) --
// If Ch != null: write fp16 output (feat), row length FEAT. Else fp32 to C (+bias).
__global__ void __launch_bounds__(256, 2) gemm_mma(
    const __half* __restrict__ A,
    const __half* __restrict__ B, float* __restrict__ C, __half* __restrict__ Ch,
    const float* __restrict__ bias, int M, int Ncols,
    const float* __restrict__ al, const float* __restrict__ ar,
    float* __restrict__ elO, float* __restrict__ erO)
{
    extern __shared__ char smem[];
    const uint32_t sbase = smem_u32(smem);
    const int tid = threadIdx.x;
    const int lane = tid & 31;
    const int warp = tid >> 5;
    const int wm = (warp & 1) * 64;
    const int wn = (warp >> 1) * 32;
    const long bm = (long)blockIdx.x * 128;
    const int bn  = blockIdx.y * 128;

    float acc[4][4][4];
#pragma unroll
    for (int i = 0; i < 4; i++)
#pragma unroll
        for (int j = 0; j < 4; j++)
#pragma unroll
            for (int q = 0; q < 4; q++) acc[i][j][q] = 0.f;

    const int NITER = 8;   // single pass: 8 k-chunks of 32 (K=256)

    auto issue = [&](int it) {
        const int kc = it;
        const uint32_t sa = sbase + (it % STAGES) * STAGE_BYTES;
        const uint32_t sb = sa + TILE_BYTES;
#pragma unroll
        for (int q = 0; q < 2; q++) {
            int ix = tid * 2 + q;
            int row = ix >> 2;
            int ch  = ix & 3;
            long arow = bm + row;
            long arc = arow < (M - 1) ? arow : (M - 1);
            cp16(sa + row * 80 + ch * 16, A + arc * 256 + kc * 32 + ch * 8,
                 (arow < M) ? 16u : 0u);
            cp16(sb + row * 80 + ch * 16, B + (long)(bn + row) * 256 + kc * 32 + ch * 8, 16u);
        }
        cp_commit();
    };

    issue(0);
    issue(1);

    for (int it = 0; it < NITER; it++) {
        // RACE FIX: on the final iteration NOTHING new was issued, so wait_group 1
        // would allow the group we are ABOUT TO READ to still be in flight.
        // (This tail race caused the R13/R14 "precision" failures and R15's
        // replay divergence.) Drain fully on the last iteration.
        if (it + 1 == NITER) cp_wait0(); else cp_wait1();
        __syncthreads();   // also orders buffer reuse (issue(it+2) overwrites buffer
                           // read at it-1, whose readers all passed this sync)
        if (it + 2 < NITER) issue(it + 2);

        const uint32_t sa = sbase + (it % STAGES) * STAGE_BYTES;
        const uint32_t sb = sa + TILE_BYTES;
#pragma unroll
        for (int ks = 0; ks < 2; ks++) {
            uint32_t a[4][4];
#pragma unroll
            for (int mt = 0; mt < 4; mt++)
                ldmx4(a[mt], sa + (wm + mt * 16 + (lane & 15)) * 80
                              + ks * 32 + (lane >> 4) * 16);
            uint32_t b[2][4];
#pragma unroll
            for (int jb = 0; jb < 2; jb++)
                ldmx4(b[jb], sb + (wn + jb * 16 + ((lane >> 4) << 3) + (lane & 7)) * 80
                              + ks * 32 + ((lane >> 3) & 1) * 16);
#pragma unroll
            for (int mt = 0; mt < 4; mt++)
#pragma unroll
                for (int nt = 0; nt < 4; nt++)
                    mma16816(acc[mt][nt], a[mt],
                             b[nt >> 1][(nt & 1) * 2], b[nt >> 1][(nt & 1) * 2 + 1]);
        }
    }

    // epilogue (+ fused attention dots)
    float* elacc = reinterpret_cast<float*>(smem + STAGES * STAGE_BYTES);
    float* eracc = elacc + 256;
    float alv[8], arv[8];
    float pel[4][2] = {}, per_[4][2] = {};
    if (al) {
        elacc[tid] = 0.f; eracc[tid] = 0.f;
#pragma unroll
        for (int nt = 0; nt < 4; nt++) {
            int c0 = bn + wn + nt * 8 + (lane & 3) * 2;
            alv[nt * 2]     = al[c0];
            alv[nt * 2 + 1] = al[c0 + 1];
            arv[nt * 2]     = ar[c0];
            arv[nt * 2 + 1] = ar[c0 + 1];
        }
        __syncthreads();
    }

    const bool even = ((Ncols & 1) == 0);
#pragma unroll
    for (int mt = 0; mt < 4; mt++) {
#pragma unroll
        for (int nt = 0; nt < 4; nt++) {
            int c0 = bn + wn + nt * 8 + (lane & 3) * 2;
            float b0 = 0.f, b1 = 0.f;
            if (bias) {
                if (c0 < Ncols)     b0 = bias[c0];
                if (c0 + 1 < Ncols) b1 = bias[c0 + 1];
            }
#pragma unroll
            for (int half = 0; half < 2; half++) {
                long row = bm + wm + mt * 16 + (lane >> 2) + half * 8;
                float v0 = acc[mt][nt][half * 2 + 0];
                float v1 = acc[mt][nt][half * 2 + 1];
                if (al) {
                    pel[mt][half]  += v0 * alv[nt * 2] + v1 * alv[nt * 2 + 1];
                    per_[mt][half] += v0 * arv[nt * 2] + v1 * arv[nt * 2 + 1];
                }
                if (row >= M) continue;
                if (Ch) {
                    *reinterpret_cast<__half2*>(Ch + row * FEAT + c0) =
                        __floats2half2_rn(v0, v1);
                } else {
                    v0 += b0; v1 += b1;
                    float* crow = C + row * Ncols;
                    if (even && (c0 + 1) < Ncols) {
                        *reinterpret_cast<float2*>(crow + c0) = make_float2(v0, v1);
                    } else {
                        if (c0 < Ncols)     crow[c0] = v0;
                        if (c0 + 1 < Ncols) crow[c0 + 1] = v1;
                    }
                }
            }
        }
    }

    if (al) {
#pragma unroll
        for (int mt = 0; mt < 4; mt++)
#pragma unroll
            for (int half = 0; half < 2; half++) {
                float s1 = pel[mt][half], s2 = per_[mt][half];
                s1 += __shfl_xor_sync(0xffffffffu, s1, 1);
                s1 += __shfl_xor_sync(0xffffffffu, s1, 2);
                s2 += __shfl_xor_sync(0xffffffffu, s2, 1);
                s2 += __shfl_xor_sync(0xffffffffu, s2, 2);
                if ((lane & 3) == 0) {
                    int rl = wm + mt * 16 + (lane >> 2) + half * 8;
                    int hl = wn >> 6;
                    atomicAdd(&elacc[rl * 2 + hl], s1);
                    atomicAdd(&eracc[rl * 2 + hl], s2);
                }
            }
        __syncthreads();
        {
            int rl = tid >> 1, hl = tid & 1;
            long n = bm + rl;
            if (n < M) {
                int hg = (bn >> 6) + hl;
                elO[n * 4 + hg] = elacc[tid];
                erO[n * 4 + hg] = eracc[tid];
            }
        }
    }
}

// ---------------- CSR aggregation: one warp per dst node (fp16 feat gather) ----
__global__ void __launch_bounds__(256) agg_csr(
    const int* __restrict__ rowptr_e, const int* __restrict__ ssorted,
    const float* __restrict__ el, const float* __restrict__ er,
    const __half* __restrict__ feat, float* __restrict__ agg,
    int mode, const float* __restrict__ bias_l,
    __half* __restrict__ hout, int do_relu)
{
    int d = blockIdx.x * 8 + (threadIdx.x >> 5);
    if (d >= NODES) return;
    int lane = threadIdx.x & 31;
    int beg = rowptr_e[d], end = rowptr_e[d + 1];
    float erl = (lane < 4) ? er[(size_t)d * 4 + lane] : 0.f;
    int hsel = lane >> 3;

    float acc[8] = {};
    float den = 0.f;

    for (int i = beg; i < end; i++) {
        int s = ssorted[i];
        float exv = 0.f;
        if (lane < 4) {
            float lg = el[(size_t)s * 4 + lane] + erl;
            lg = lg > 0.f ? lg : NEG_SLOPE * lg;
            exv = __expf(lg);
            den += exv;
        }
        float ev = __shfl_sync(0xffffffffu, exv, hsel);
        uint4 fv = *reinterpret_cast<const uint4*>(feat + (size_t)s * FEAT + lane * 8);
        float2 f0 = __half22float2(*reinterpret_cast<__half2*>(&fv.x));
        float2 f1 = __half22float2(*reinterpret_cast<__half2*>(&fv.y));
        float2 f2 = __half22float2(*reinterpret_cast<__half2*>(&fv.z));
        float2 f3 = __half22float2(*reinterpret_cast<__half2*>(&fv.w));
        acc[0] += ev * f0.x; acc[1] += ev * f0.y;
        acc[2] += ev * f1.x; acc[3] += ev * f1.y;
        acc[4] += ev * f2.x; acc[5] += ev * f2.y;
        acc[6] += ev * f3.x; acc[7] += ev * f3.y;
    }

    float dh = __shfl_sync(0xffffffffu, den, hsel);
    float r = (dh > 0.f) ? (1.0f / dh) : 0.f;
#pragma unroll
    for (int q = 0; q < 8; q++) acc[q] *= r;

    float4* ag = reinterpret_cast<float4*>(agg + (size_t)d * FEAT) + lane * 2;
    if (mode >= 1) {
        float4 p0 = ag[0], p1 = ag[1];
        acc[0] += p0.x; acc[1] += p0.y; acc[2] += p0.z; acc[3] += p0.w;
        acc[4] += p1.x; acc[5] += p1.y; acc[6] += p1.z; acc[7] += p1.w;
    }
    if (mode < 2) {
        ag[0] = make_float4(acc[0], acc[1], acc[2], acc[3]);
        ag[1] = make_float4(acc[4], acc[5], acc[6], acc[7]);
        return;
    }

    // final etype: add summed bias, relu, fp16 convert
    int c = lane * 8;
#pragma unroll
    for (int q = 0; q < 8; q++)
        acc[q] += bias_l[c + q] + bias_l[256 + c + q] + bias_l[512 + c + q];
    if (do_relu) {
#pragma unroll
        for (int q = 0; q < 8; q++) acc[q] = fmaxf(acc[q], 0.f);
    }
    __half2* ph = reinterpret_cast<__half2*>(hout + (size_t)d * FEAT + c);
#pragma unroll
    for (int q = 0; q < 4; q++)
        ph[q] = __floats2half2_rn(acc[q * 2], acc[q * 2 + 1]);
}

// ---------------- launch ----------------
extern "C" void kernel_launch(void* const* d_in, const int* in_sizes, int n_in,
                              void* d_out, int out_size)
{
    const float* x      = (const float*)d_in[0];
    const float* W      = (const float*)d_in[1];
    const float* attn_l = (const float*)d_in[2];
    const float* attn_r = (const float*)d_in[3];
    const float* bias   = (const float*)d_in[4];
    const float* W_out  = (const float*)d_in[5];
    const float* b_out  = (const float*)d_in[6];
    const int*   src    = (const int*)d_in[7];
    const int*   dst    = (const int*)d_in[8];

    float *agg, *el, *er;
    __half *feat, *ah, *whi, *wohi;
    int *rowptr, *head, *blksum, *ssorted;
    cudaGetSymbolAddress((void**)&feat,    g_feat);
    cudaGetSymbolAddress((void**)&agg,     g_agg);
    cudaGetSymbolAddress((void**)&el,      g_el);
    cudaGetSymbolAddress((void**)&er,      g_er);
    cudaGetSymbolAddress((void**)&ah,      g_ah);
    cudaGetSymbolAddress((void**)&whi,     g_whi);
    cudaGetSymbolAddress((void**)&wohi,    g_wohi);
    cudaGetSymbolAddress((void**)&rowptr,  g_rowptr);
    cudaGetSymbolAddress((void**)&head,    g_head);
    cudaGetSymbolAddress((void**)&blksum,  g_blksum);
    cudaGetSymbolAddress((void**)&ssorted, g_ssorted);

    cudaFuncSetAttribute(gemm_mma, cudaFuncAttributeMaxDynamicSharedMemorySize, GEMM_SMEM);

    // lazy one-time stream/event setup (first call = uncaptured correctness run)
    static cudaStream_t s1 = nullptr;
    static cudaEvent_t evStart, evGemm[6], evAgg[6], evLayer[2];
    if (!s1) {
        cudaStreamCreateWithFlags(&s1, cudaStreamNonBlocking);
        cudaEventCreateWithFlags(&evStart, cudaEventDisableTiming);
        for (int i = 0; i < 6; i++) {
            cudaEventCreateWithFlags(&evGemm[i], cudaEventDisableTiming);
            cudaEventCreateWithFlags(&evAgg[i],  cudaEventDisableTiming);
        }
        for (int i = 0; i < 2; i++) cudaEventCreateWithFlags(&evLayer[i], cudaEventDisableTiming);
    }

    // fork side stream from capture stream
    cudaEventRecord(evStart, 0);
    cudaStreamWaitEvent(s1, evStart, 0);

    // main stream: weight/input prep
    prep_w<<<(6 * FEAT * FEAT + 255) / 256, 256>>>(W, whi);
    prep_wout<<<(NPAD_OUT * FEAT + 255) / 256, 256>>>(W_out, wohi);
    conv_f32<<<(NODES * FEAT / 4 + 255) / 256, 256>>>(x, ah, NODES * FEAT / 4);

    // side stream: CSR build (overlaps prep + first GEMM)
    zero_i<<<(NSEG + 255) / 256, 256, 0, s1>>>(head, NSEG);
    hist_k<<<(TOTE + 255) / 256, 256, 0, s1>>>(dst, head);
    scan_l1<<<NBLK, SBLK, 0, s1>>>(head, rowptr, blksum);
    scan_l2<<<1, 1024, 0, s1>>>(blksum, rowptr);
    scan_l3<<<(NSEG + 255) / 256, 256, 0, s1>>>(rowptr, blksum, head);
    scatter_k<<<(TOTE + 255) / 256, 256, 0, s1>>>(src, dst, head, ssorted);

    dim3 feat_grid(GRID_M, 2);
    dim3 out_grid(GRID_M, 3);
    const int AGG_BLOCKS = (NODES + 7) / 8;

    for (int l = 0; l < 2; l++) {
        for (int e = 0; e < 3; e++) {
            int le = l * 3 + e;
            int pb = e & 1;
            __half* feat_e = feat + (size_t)pb * NODES * FEAT;
            float* el_e = el + (size_t)pb * NODES * 4;
            float* er_e = er + (size_t)pb * NODES * 4;
            // ANTI-RACE: gemm(e=2) reuses parity-0 buffers still read by agg(e=0)
            if (e == 2) cudaStreamWaitEvent(0, evAgg[l * 3], 0);
            gemm_mma<<<feat_grid, 256, GEMM_SMEM>>>(
                ah, whi + (size_t)le * FEAT * FEAT, nullptr, feat_e, nullptr,
                NODES, FEAT,
                attn_l + le * FEAT, attn_r + le * FEAT, el_e, er_e);
            cudaEventRecord(evGemm[le], 0);
            cudaStreamWaitEvent(s1, evGemm[le], 0);
            agg_csr<<<AGG_BLOCKS, 256, 0, s1>>>(
                rowptr + e * NODES, ssorted, el_e, er_e, feat_e, agg,
                e, bias + l * 3 * FEAT, ah, (l == 0) ? 1 : 0);
            cudaEventRecord(evAgg[le], s1);
        }
        // layer boundary: main must wait for agg2 (writes ah)
        cudaEventRecord(evLayer[l], s1);
        cudaStreamWaitEvent(0, evLayer[l], 0);
    }

    gemm_mma<<<out_grid, 256, GEMM_SMEM>>>(
        ah, wohi, (float*)d_out, nullptr, b_out, NODES, CLASSES,
        nullptr, nullptr, nullptr, nullptr);
}